// round 3
// baseline (speedup 1.0000x reference)
#include <cuda_runtime.h>
#include <cuda_fp16.h>

#define D 128
#define NMAX 100000
#define PAD 20   // shared row stride in words: 20 mod 32 makes frag loads conflict-free

// h_src = g_h[0], h_dst = g_h[1], stored fp16 (51.2 MB total -> fits L2)
__device__ __half g_h[2][(size_t)NMAX * D];
__device__ int g_idx64;

__global__ void detect_idx_kernel(const long long* __restrict__ p, int N) {
    int ok = 0;
#pragma unroll
    for (int i = 0; i < 16; i++) {
        long long v = p[i];
        if (v >= 0 && v < (long long)N) ok++;
    }
    g_idx64 = (ok >= 12) ? 1 : 0;
}

__device__ __forceinline__ unsigned f2tf32(float f) {
    unsigned u;
    asm("cvt.rna.tf32.f32 %0, %1;" : "=r"(u) : "f"(f));
    return u;
}

__device__ __forceinline__ void mma_tf32(float c[4], unsigned a0, unsigned a1,
                                         unsigned a2, unsigned a3,
                                         unsigned b0, unsigned b1) {
    asm volatile(
        "mma.sync.aligned.m16n8k8.row.col.f32.tf32.tf32.f32 "
        "{%0,%1,%2,%3},{%4,%5,%6,%7},{%8,%9},{%0,%1,%2,%3};"
        : "+f"(c[0]), "+f"(c[1]), "+f"(c[2]), "+f"(c[3])
        : "r"(a0), "r"(a1), "r"(a2), "r"(a3), "r"(b0), "r"(b1));
}

// ---------------------------------------------------------------------------
// Node GEMM (tensor cores, tf32): h[n,j] = sum_k x[n,k]*W[j,k] + b[j], fp16 out
// Block: 128 rows x 128 cols. 8 warps in 2x4 grid; warp tile 64x32.
// mma m16n8k8: A row-major (x), B col-major = W row-major natural.
// ---------------------------------------------------------------------------
__global__ __launch_bounds__(256, 2) void node_gemm_tc(
    const float* __restrict__ x, const float* __restrict__ W,
    const float* __restrict__ b, int which, int N)
{
    __shared__ unsigned As[128][PAD];   // tf32 bits, [row][k]
    __shared__ unsigned Bs[128][PAD];   // tf32 bits, [j][k]

    __half* __restrict__ out = g_h[which];

    const int tid  = threadIdx.x;
    const int wid  = tid >> 5;
    const int lane = tid & 31;
    const int wm   = (wid >> 2) * 64;     // warp M offset: 0 / 64
    const int wn   = (wid & 3) * 32;      // warp N offset: 0/32/64/96
    const int row0 = blockIdx.x * 128;
    const int tg   = lane >> 2;           // 0..7
    const int tr   = lane & 3;            // 0..3

    float acc[4][4][4];                   // [mt][nt][frag]
#pragma unroll
    for (int i = 0; i < 4; i++)
#pragma unroll
        for (int j = 0; j < 4; j++)
#pragma unroll
            for (int k = 0; k < 4; k++) acc[i][j][k] = 0.0f;

    const int lrow = tid >> 1;            // 0..127
    const int lcol = (tid & 1) * 8;       // 0 or 8

    for (int kt = 0; kt < 128; kt += 16) {
        float4 v0 = make_float4(0.f,0.f,0.f,0.f), v1 = v0;
        if (row0 + lrow < N) {
            const float* xr = x + (size_t)(row0 + lrow) * D + kt + lcol;
            v0 = *(const float4*)xr;
            v1 = *(const float4*)(xr + 4);
        }
        As[lrow][lcol+0] = f2tf32(v0.x); As[lrow][lcol+1] = f2tf32(v0.y);
        As[lrow][lcol+2] = f2tf32(v0.z); As[lrow][lcol+3] = f2tf32(v0.w);
        As[lrow][lcol+4] = f2tf32(v1.x); As[lrow][lcol+5] = f2tf32(v1.y);
        As[lrow][lcol+6] = f2tf32(v1.z); As[lrow][lcol+7] = f2tf32(v1.w);

        const float* wr = W + (size_t)lrow * D + kt + lcol;
        float4 w0 = *(const float4*)wr;
        float4 w1 = *(const float4*)(wr + 4);
        Bs[lrow][lcol+0] = f2tf32(w0.x); Bs[lrow][lcol+1] = f2tf32(w0.y);
        Bs[lrow][lcol+2] = f2tf32(w0.z); Bs[lrow][lcol+3] = f2tf32(w0.w);
        Bs[lrow][lcol+4] = f2tf32(w1.x); Bs[lrow][lcol+5] = f2tf32(w1.y);
        Bs[lrow][lcol+6] = f2tf32(w1.z); Bs[lrow][lcol+7] = f2tf32(w1.w);
        __syncthreads();

#pragma unroll
        for (int kk = 0; kk < 16; kk += 8) {
            unsigned bf[4][2];
#pragma unroll
            for (int nt = 0; nt < 4; nt++) {
                bf[nt][0] = Bs[wn + nt*8 + tg][kk + tr];
                bf[nt][1] = Bs[wn + nt*8 + tg][kk + tr + 4];
            }
#pragma unroll
            for (int mt = 0; mt < 4; mt++) {
                const int ar = wm + mt*16 + tg;
                unsigned a0 = As[ar    ][kk + tr];
                unsigned a1 = As[ar + 8][kk + tr];
                unsigned a2 = As[ar    ][kk + tr + 4];
                unsigned a3 = As[ar + 8][kk + tr + 4];
#pragma unroll
                for (int nt = 0; nt < 4; nt++)
                    mma_tf32(acc[mt][nt], a0, a1, a2, a3, bf[nt][0], bf[nt][1]);
            }
        }
        __syncthreads();
    }

    // Epilogue: add bias, convert to fp16, store (half2 per frag row).
#pragma unroll
    for (int mt = 0; mt < 4; mt++) {
#pragma unroll
        for (int nt = 0; nt < 4; nt++) {
            const int cg = wn + nt*8 + 2*tr;
            const float bb0 = b[cg], bb1 = b[cg + 1];
            const int r0g = row0 + wm + mt*16 + tg;
            const int r1g = r0g + 8;
            if (r0g < N) {
                __half2 h = __floats2half2_rn(acc[mt][nt][0] + bb0,
                                              acc[mt][nt][1] + bb1);
                *(__half2*)(out + (size_t)r0g * D + cg) = h;
            }
            if (r1g < N) {
                __half2 h = __floats2half2_rn(acc[mt][nt][2] + bb0,
                                              acc[mt][nt][3] + bb1);
                *(__half2*)(out + (size_t)r1g * D + cg) = h;
            }
        }
    }
}

// ---------------------------------------------------------------------------
// Edge pass: warp-per-edge, fp16 gathers (256B/edge/array), fp32 outputs.
// ---------------------------------------------------------------------------
__global__ __launch_bounds__(256) void edge_kernel(
    const void* __restrict__ srcp, const void* __restrict__ dstp,
    const float* __restrict__ W_out, const float* __restrict__ b_out,
    float* __restrict__ score, float* __restrict__ embs,
    long long E, int N)
{
    __shared__ float4 w0s[32];
    __shared__ float4 w1s[32];
    __shared__ float2 sc[8];

    const int tid = threadIdx.x;
    if (tid < 64) {
        float4 w = ((const float4*)W_out)[tid];
        if (tid < 32) w0s[tid] = w; else w1s[tid - 32] = w;
    }
    __syncthreads();

    const int warp = tid >> 5;
    const int lane = tid & 31;
    const long long e = (long long)blockIdx.x * 8 + warp;
    const __half* __restrict__ hs = g_h[0];
    const __half* __restrict__ hd = g_h[1];

    if (e < E) {
        int s, d;
        if (g_idx64) {
            s = (int)((const long long*)srcp)[e];
            d = (int)((const long long*)dstp)[e];
        } else {
            s = ((const int*)srcp)[e];
            d = ((const int*)dstp)[e];
        }
        s = min(max(s, 0), N - 1);
        d = min(max(d, 0), N - 1);

        // 4 halves per lane from each array (8B loads, 256B/warp, coalesced)
        const uint2 pa = ((const uint2*)hs)[(size_t)s * 32 + lane];
        const uint2 pb = ((const uint2*)hd)[(size_t)d * 32 + lane];
        float2 a01 = __half22float2(*(const __half2*)&pa.x);
        float2 a23 = __half22float2(*(const __half2*)&pa.y);
        float2 b01 = __half22float2(*(const __half2*)&pb.x);
        float2 b23 = __half22float2(*(const __half2*)&pb.y);

        float4 v;
        v.x = fmaxf(a01.x + b01.x, 0.0f);
        v.y = fmaxf(a01.y + b01.y, 0.0f);
        v.z = fmaxf(a23.x + b23.x, 0.0f);
        v.w = fmaxf(a23.y + b23.y, 0.0f);

        __stcs(&((float4*)embs)[(size_t)e * 32 + lane], v);

        const float4 w0 = w0s[lane];
        const float4 w1 = w1s[lane];
        float d0 = v.x * w0.x + v.y * w0.y + v.z * w0.z + v.w * w0.w;
        float d1 = v.x * w1.x + v.y * w1.y + v.z * w1.z + v.w * w1.w;
#pragma unroll
        for (int o = 16; o > 0; o >>= 1) {
            d0 += __shfl_xor_sync(0xffffffffu, d0, o);
            d1 += __shfl_xor_sync(0xffffffffu, d1, o);
        }
        if (lane == 0)
            sc[warp] = make_float2(d0 + b_out[0], d1 + b_out[1]);
    }
    __syncthreads();

    const long long base = (long long)blockIdx.x * 8;
    if (tid < 8 && base + tid < E)
        __stcs(&((float2*)score)[base + tid], sc[tid]);
}

extern "C" void kernel_launch(void* const* d_in, const int* in_sizes, int n_in,
                              void* d_out, int out_size)
{
    const float* x     = (const float*)d_in[0];
    const void*  src   = d_in[1];
    const void*  dst   = d_in[2];
    const float* W_src = (const float*)d_in[3];
    const float* b_src = (const float*)d_in[4];
    const float* W_dst = (const float*)d_in[5];
    const float* b_dst = (const float*)d_in[6];
    const float* W_out = (const float*)d_in[7];
    const float* b_out = (const float*)d_in[8];

    const int N = in_sizes[0] / D;
    const long long E = in_sizes[1];

    float* out   = (float*)d_out;
    float* score = out;                       // [E, 2]
    float* embs  = out + (size_t)E * 2;       // [E, 128]

    detect_idx_kernel<<<1, 1>>>((const long long*)src, N);

    const int gb = (N + 127) / 128;
    node_gemm_tc<<<gb, 256>>>(x, W_src, b_src, 0, N);
    node_gemm_tc<<<gb, 256>>>(x, W_dst, b_dst, 1, N);

    const int eb = (int)((E + 7) / 8);
    edge_kernel<<<eb, 256>>>(src, dst, W_out, b_out, score, embs, E, N);
}

// round 5
// speedup vs baseline: 1.6615x; 1.6615x over previous
#include <cuda_runtime.h>
#include <cuda_fp16.h>

#define D 128
#define NMAX 100000
#define PAD 20

__device__ __half g_h[2][(size_t)NMAX * D];
__device__ int g_idx64;

__global__ void detect_idx_kernel(const long long* __restrict__ p, int N) {
    int ok = 0;
#pragma unroll
    for (int i = 0; i < 16; i++) {
        long long v = p[i];
        if (v >= 0 && v < (long long)N) ok++;
    }
    g_idx64 = (ok >= 12) ? 1 : 0;
}

__device__ __forceinline__ unsigned f2tf32(float f) {
    unsigned u;
    asm("cvt.rna.tf32.f32 %0, %1;" : "=r"(u) : "f"(f));
    return u;
}

__device__ __forceinline__ void mma_tf32(float c[4], unsigned a0, unsigned a1,
                                         unsigned a2, unsigned a3,
                                         unsigned b0, unsigned b1) {
    asm volatile(
        "mma.sync.aligned.m16n8k8.row.col.f32.tf32.tf32.f32 "
        "{%0,%1,%2,%3},{%4,%5,%6,%7},{%8,%9},{%0,%1,%2,%3};"
        : "+f"(c[0]), "+f"(c[1]), "+f"(c[2]), "+f"(c[3])
        : "r"(a0), "r"(a1), "r"(a2), "r"(a3), "r"(b0), "r"(b1));
}

// ---------------------------------------------------------------------------
// Node GEMM (tf32 tensor cores): h[n,j] = sum_k x[n,k]*W[j,k] + b[j], fp16 out
// ---------------------------------------------------------------------------
__global__ __launch_bounds__(256, 2) void node_gemm_tc(
    const float* __restrict__ x, const float* __restrict__ W,
    const float* __restrict__ b, int which, int N)
{
    __shared__ unsigned As[128][PAD];
    __shared__ unsigned Bs[128][PAD];

    __half* __restrict__ out = g_h[which];

    const int tid  = threadIdx.x;
    const int wid  = tid >> 5;
    const int lane = tid & 31;
    const int wm   = (wid >> 2) * 64;
    const int wn   = (wid & 3) * 32;
    const int row0 = blockIdx.x * 128;
    const int tg   = lane >> 2;
    const int tr   = lane & 3;

    float acc[4][4][4];
#pragma unroll
    for (int i = 0; i < 4; i++)
#pragma unroll
        for (int j = 0; j < 4; j++)
#pragma unroll
            for (int k = 0; k < 4; k++) acc[i][j][k] = 0.0f;

    const int lrow = tid >> 1;
    const int lcol = (tid & 1) * 8;

    for (int kt = 0; kt < 128; kt += 16) {
        float4 v0 = make_float4(0.f,0.f,0.f,0.f), v1 = v0;
        if (row0 + lrow < N) {
            const float* xr = x + (size_t)(row0 + lrow) * D + kt + lcol;
            v0 = *(const float4*)xr;
            v1 = *(const float4*)(xr + 4);
        }
        As[lrow][lcol+0] = f2tf32(v0.x); As[lrow][lcol+1] = f2tf32(v0.y);
        As[lrow][lcol+2] = f2tf32(v0.z); As[lrow][lcol+3] = f2tf32(v0.w);
        As[lrow][lcol+4] = f2tf32(v1.x); As[lrow][lcol+5] = f2tf32(v1.y);
        As[lrow][lcol+6] = f2tf32(v1.z); As[lrow][lcol+7] = f2tf32(v1.w);

        const float* wr = W + (size_t)lrow * D + kt + lcol;
        float4 w0 = *(const float4*)wr;
        float4 w1 = *(const float4*)(wr + 4);
        Bs[lrow][lcol+0] = f2tf32(w0.x); Bs[lrow][lcol+1] = f2tf32(w0.y);
        Bs[lrow][lcol+2] = f2tf32(w0.z); Bs[lrow][lcol+3] = f2tf32(w0.w);
        Bs[lrow][lcol+4] = f2tf32(w1.x); Bs[lrow][lcol+5] = f2tf32(w1.y);
        Bs[lrow][lcol+6] = f2tf32(w1.z); Bs[lrow][lcol+7] = f2tf32(w1.w);
        __syncthreads();

#pragma unroll
        for (int kk = 0; kk < 16; kk += 8) {
            unsigned bf[4][2];
#pragma unroll
            for (int nt = 0; nt < 4; nt++) {
                bf[nt][0] = Bs[wn + nt*8 + tg][kk + tr];
                bf[nt][1] = Bs[wn + nt*8 + tg][kk + tr + 4];
            }
#pragma unroll
            for (int mt = 0; mt < 4; mt++) {
                const int ar = wm + mt*16 + tg;
                unsigned a0 = As[ar    ][kk + tr];
                unsigned a1 = As[ar + 8][kk + tr];
                unsigned a2 = As[ar    ][kk + tr + 4];
                unsigned a3 = As[ar + 8][kk + tr + 4];
#pragma unroll
                for (int nt = 0; nt < 4; nt++)
                    mma_tf32(acc[mt][nt], a0, a1, a2, a3, bf[nt][0], bf[nt][1]);
            }
        }
        __syncthreads();
    }

#pragma unroll
    for (int mt = 0; mt < 4; mt++) {
#pragma unroll
        for (int nt = 0; nt < 4; nt++) {
            const int cg = wn + nt*8 + 2*tr;
            const float bb0 = b[cg], bb1 = b[cg + 1];
            const int r0g = row0 + wm + mt*16 + tg;
            const int r1g = r0g + 8;
            if (r0g < N) {
                __half2 h = __floats2half2_rn(acc[mt][nt][0] + bb0,
                                              acc[mt][nt][1] + bb1);
                *(__half2*)(out + (size_t)r0g * D + cg) = h;
            }
            if (r1g < N) {
                __half2 h = __floats2half2_rn(acc[mt][nt][2] + bb0,
                                              acc[mt][nt][3] + bb1);
                *(__half2*)(out + (size_t)r1g * D + cg) = h;
            }
        }
    }
}

// ---------------------------------------------------------------------------
// Edge pass: 16 lanes per edge, 2 edges per warp, 16 edges per 256-thr block.
// Lane sl in [0,16) covers elements [sl*8, sl*8+8): one uint4 (8 halves) per
// h array -> full 128-wide row per edge. half2 add+relu, 2x STG.128,
// 8-shfl score reduction per edge.
// ---------------------------------------------------------------------------
__global__ __launch_bounds__(256) void edge_kernel(
    const void* __restrict__ srcp, const void* __restrict__ dstp,
    const float* __restrict__ W_out, const float* __restrict__ b_out,
    float* __restrict__ score, float* __restrict__ embs,
    long long E, int N)
{
    __shared__ float4 ws[64];      // W_out row0 (32 float4) then row1 (32)
    __shared__ float2 sc[16];

    const int tid = threadIdx.x;
    if (tid < 64) ws[tid] = ((const float4*)W_out)[tid];
    __syncthreads();

    const int warp = tid >> 5;
    const int lane = tid & 31;
    const int sub  = lane >> 4;        // edge within warp (0..1)
    const int sl   = lane & 15;        // lane within edge (0..15)
    const long long e = (long long)blockIdx.x * 16 + warp * 2 + sub;

    const __half* __restrict__ hs = g_h[0];
    const __half* __restrict__ hd = g_h[1];

    if (e < E) {
        int s, d;
        if (g_idx64) {
            s = (int)((const long long*)srcp)[e];
            d = (int)((const long long*)dstp)[e];
        } else {
            s = ((const int*)srcp)[e];
            d = ((const int*)dstp)[e];
        }
        s = min(max(s, 0), N - 1);
        d = min(max(d, 0), N - 1);

        // 16B per lane: elements [sl*8, sl*8+8) of the 128-half row (16 uint4/row).
        const uint4 pa = ((const uint4*)hs)[(size_t)s * 16 + sl];
        const uint4 pb = ((const uint4*)hd)[(size_t)d * 16 + sl];

        const __half2 z = __float2half2_rn(0.0f);
        __half2 v0 = __hmax2(__hadd2(*(const __half2*)&pa.x, *(const __half2*)&pb.x), z);
        __half2 v1 = __hmax2(__hadd2(*(const __half2*)&pa.y, *(const __half2*)&pb.y), z);
        __half2 v2 = __hmax2(__hadd2(*(const __half2*)&pa.z, *(const __half2*)&pb.z), z);
        __half2 v3 = __hmax2(__hadd2(*(const __half2*)&pa.w, *(const __half2*)&pb.w), z);

        float2 f0 = __half22float2(v0);
        float2 f1 = __half22float2(v1);
        float2 f2 = __half22float2(v2);
        float2 f3 = __half22float2(v3);

        float* ep = embs + (size_t)e * D + sl * 8;
        *(float4*)(ep)     = make_float4(f0.x, f0.y, f1.x, f1.y);
        *(float4*)(ep + 4) = make_float4(f2.x, f2.y, f3.x, f3.y);

        // W_out fragments for this lane's 8 columns (cols sl*8 .. sl*8+7).
        const float4 wa0 = ws[sl * 2];
        const float4 wa1 = ws[sl * 2 + 1];
        const float4 wb0 = ws[32 + sl * 2];
        const float4 wb1 = ws[32 + sl * 2 + 1];

        float d0 = f0.x*wa0.x + f0.y*wa0.y + f1.x*wa0.z + f1.y*wa0.w
                 + f2.x*wa1.x + f2.y*wa1.y + f3.x*wa1.z + f3.y*wa1.w;
        float d1 = f0.x*wb0.x + f0.y*wb0.y + f1.x*wb0.z + f1.y*wb0.w
                 + f2.x*wb1.x + f2.y*wb1.y + f3.x*wb1.z + f3.y*wb1.w;

#pragma unroll
        for (int o = 8; o > 0; o >>= 1) {
            d0 += __shfl_xor_sync(0xffffffffu, d0, o);
            d1 += __shfl_xor_sync(0xffffffffu, d1, o);
        }
        if (sl == 0)
            sc[warp * 2 + sub] = make_float2(d0 + b_out[0], d1 + b_out[1]);
    }
    __syncthreads();

    const long long base = (long long)blockIdx.x * 16;
    if (tid < 16 && base + tid < E)
        ((float2*)score)[base + tid] = sc[tid];
}

extern "C" void kernel_launch(void* const* d_in, const int* in_sizes, int n_in,
                              void* d_out, int out_size)
{
    const float* x     = (const float*)d_in[0];
    const void*  src   = d_in[1];
    const void*  dst   = d_in[2];
    const float* W_src = (const float*)d_in[3];
    const float* b_src = (const float*)d_in[4];
    const float* W_dst = (const float*)d_in[5];
    const float* b_dst = (const float*)d_in[6];
    const float* W_out = (const float*)d_in[7];
    const float* b_out = (const float*)d_in[8];

    const int N = in_sizes[0] / D;
    const long long E = in_sizes[1];

    float* out   = (float*)d_out;
    float* score = out;                       // [E, 2]
    float* embs  = out + (size_t)E * 2;       // [E, 128]

    detect_idx_kernel<<<1, 1>>>((const long long*)src, N);

    const int gb = (N + 127) / 128;
    node_gemm_tc<<<gb, 256>>>(x, W_src, b_src, 0, N);
    node_gemm_tc<<<gb, 256>>>(x, W_dst, b_dst, 1, N);

    const int eb = (int)((E + 15) / 16);
    edge_kernel<<<eb, 256>>>(src, dst, W_out, b_out, score, embs, E, N);
}

// round 6
// speedup vs baseline: 1.8666x; 1.1235x over previous
#include <cuda_runtime.h>
#include <cuda_fp16.h>

#define D 128
#define NMAX 100000
#define PAD 20

__device__ __half g_h[2][(size_t)NMAX * D];
__device__ int g_idx64;

__global__ void detect_idx_kernel(const long long* __restrict__ p, int N) {
    int ok = 0;
#pragma unroll
    for (int i = 0; i < 16; i++) {
        long long v = p[i];
        if (v >= 0 && v < (long long)N) ok++;
    }
    g_idx64 = (ok >= 12) ? 1 : 0;
}

__device__ __forceinline__ unsigned f2tf32(float f) {
    unsigned u;
    asm("cvt.rna.tf32.f32 %0, %1;" : "=r"(u) : "f"(f));
    return u;
}

__device__ __forceinline__ void mma_tf32(float c[4], unsigned a0, unsigned a1,
                                         unsigned a2, unsigned a3,
                                         unsigned b0, unsigned b1) {
    asm volatile(
        "mma.sync.aligned.m16n8k8.row.col.f32.tf32.tf32.f32 "
        "{%0,%1,%2,%3},{%4,%5,%6,%7},{%8,%9},{%0,%1,%2,%3};"
        : "+f"(c[0]), "+f"(c[1]), "+f"(c[2]), "+f"(c[3])
        : "r"(a0), "r"(a1), "r"(a2), "r"(a3), "r"(b0), "r"(b1));
}

// ---------------------------------------------------------------------------
// Fused node GEMM: one pass over x computes BOTH h_src and h_dst.
// 512 threads: warps 0-7 -> W_src half, warps 8-15 -> W_dst half.
// Per half: 8-warp 128x128 tile, warp tile 64x32, mma m16n8k8 tf32.
// ---------------------------------------------------------------------------
__global__ __launch_bounds__(512, 1) void node_gemm_fused(
    const float* __restrict__ x,
    const float* __restrict__ Wsrc, const float* __restrict__ bsrc,
    const float* __restrict__ Wdst, const float* __restrict__ bdst, int N)
{
    __shared__ unsigned As[128][PAD];
    __shared__ unsigned Bs[2][128][PAD];

    const int tid  = threadIdx.x;
    const int wid  = tid >> 5;
    const int lane = tid & 31;
    const int half = wid >> 3;            // 0 = src, 1 = dst
    const int w    = wid & 7;
    const int wm   = (w >> 2) * 64;
    const int wn   = (w & 3) * 32;
    const int row0 = blockIdx.x * 128;
    const int tg   = lane >> 2;
    const int tr   = lane & 3;

    const float* __restrict__ Wh = half ? Wdst : Wsrc;
    const float* __restrict__ bh = half ? bdst : bsrc;
    __half* __restrict__ out = g_h[half];

    float acc[4][4][4];
#pragma unroll
    for (int i = 0; i < 4; i++)
#pragma unroll
        for (int j = 0; j < 4; j++)
#pragma unroll
            for (int k = 0; k < 4; k++) acc[i][j][k] = 0.0f;

    // Cooperative tile loads: 128x16 words per tile, 512 thr x 4 words each.
    const int lrow  = tid >> 2;           // 0..127
    const int lcol4 = (tid & 3) * 4;      // 0,4,8,12

    for (int kt = 0; kt < 128; kt += 16) {
        float4 av = make_float4(0.f, 0.f, 0.f, 0.f);
        if (row0 + lrow < N)
            av = *(const float4*)(x + (size_t)(row0 + lrow) * D + kt + lcol4);
        As[lrow][lcol4+0] = f2tf32(av.x); As[lrow][lcol4+1] = f2tf32(av.y);
        As[lrow][lcol4+2] = f2tf32(av.z); As[lrow][lcol4+3] = f2tf32(av.w);

        const float4 ws = *(const float4*)(Wsrc + (size_t)lrow * D + kt + lcol4);
        Bs[0][lrow][lcol4+0] = f2tf32(ws.x); Bs[0][lrow][lcol4+1] = f2tf32(ws.y);
        Bs[0][lrow][lcol4+2] = f2tf32(ws.z); Bs[0][lrow][lcol4+3] = f2tf32(ws.w);

        const float4 wd = *(const float4*)(Wdst + (size_t)lrow * D + kt + lcol4);
        Bs[1][lrow][lcol4+0] = f2tf32(wd.x); Bs[1][lrow][lcol4+1] = f2tf32(wd.y);
        Bs[1][lrow][lcol4+2] = f2tf32(wd.z); Bs[1][lrow][lcol4+3] = f2tf32(wd.w);
        __syncthreads();

#pragma unroll
        for (int kk = 0; kk < 16; kk += 8) {
            unsigned bf[4][2];
#pragma unroll
            for (int nt = 0; nt < 4; nt++) {
                bf[nt][0] = Bs[half][wn + nt*8 + tg][kk + tr];
                bf[nt][1] = Bs[half][wn + nt*8 + tg][kk + tr + 4];
            }
#pragma unroll
            for (int mt = 0; mt < 4; mt++) {
                const int ar = wm + mt*16 + tg;
                unsigned a0 = As[ar    ][kk + tr];
                unsigned a1 = As[ar + 8][kk + tr];
                unsigned a2 = As[ar    ][kk + tr + 4];
                unsigned a3 = As[ar + 8][kk + tr + 4];
#pragma unroll
                for (int nt = 0; nt < 4; nt++)
                    mma_tf32(acc[mt][nt], a0, a1, a2, a3, bf[nt][0], bf[nt][1]);
            }
        }
        __syncthreads();
    }

#pragma unroll
    for (int mt = 0; mt < 4; mt++) {
#pragma unroll
        for (int nt = 0; nt < 4; nt++) {
            const int cg = wn + nt*8 + 2*tr;
            const float bb0 = bh[cg], bb1 = bh[cg + 1];
            const int r0g = row0 + wm + mt*16 + tg;
            const int r1g = r0g + 8;
            if (r0g < N) {
                __half2 h = __floats2half2_rn(acc[mt][nt][0] + bb0,
                                              acc[mt][nt][1] + bb1);
                *(__half2*)(out + (size_t)r0g * D + cg) = h;
            }
            if (r1g < N) {
                __half2 h = __floats2half2_rn(acc[mt][nt][2] + bb0,
                                              acc[mt][nt][3] + bb1);
                *(__half2*)(out + (size_t)r1g * D + cg) = h;
            }
        }
    }
}

// ---------------------------------------------------------------------------
// Edge pass: 16 lanes/edge, 2 edges/warp. Lane sl owns cols [sl*4, sl*4+4)
// and [64+sl*4, 64+sl*4+4), so each STG.128 covers a CONTIGUOUS 256B per
// edge (full 128B lines -> minimal store wavefronts). Gathers are LDG.64,
// one full line per edge per instruction.
// ---------------------------------------------------------------------------
__global__ __launch_bounds__(256) void edge_kernel(
    const void* __restrict__ srcp, const void* __restrict__ dstp,
    const float* __restrict__ W_out, const float* __restrict__ b_out,
    float* __restrict__ score, float* __restrict__ embs,
    long long E, int N)
{
    __shared__ float4 ws[64];      // row0: [0..31], row1: [32..63]
    __shared__ float2 sc[16];

    const int tid = threadIdx.x;
    if (tid < 64) ws[tid] = ((const float4*)W_out)[tid];
    __syncthreads();

    const int warp = tid >> 5;
    const int lane = tid & 31;
    const int sub  = lane >> 4;        // edge within warp
    const int sl   = lane & 15;        // lane within edge
    const long long e = (long long)blockIdx.x * 16 + warp * 2 + sub;

    const __half* __restrict__ hs = g_h[0];
    const __half* __restrict__ hd = g_h[1];

    if (e < E) {
        int s, d;
        if (g_idx64) {
            s = (int)((const long long*)srcp)[e];
            d = (int)((const long long*)dstp)[e];
        } else {
            s = ((const int*)srcp)[e];
            d = ((const int*)dstp)[e];
        }
        s = min(max(s, 0), N - 1);
        d = min(max(d, 0), N - 1);

        const __half* rs = hs + (size_t)s * D;
        const __half* rd = hd + (size_t)d * D;

        // lo: cols [sl*4, +4), hi: cols [64+sl*4, +4)  (uint2 = 4 halves)
        const uint2 sa_lo = ((const uint2*)rs)[sl];
        const uint2 sa_hi = ((const uint2*)(rs + 64))[sl];
        const uint2 da_lo = ((const uint2*)rd)[sl];
        const uint2 da_hi = ((const uint2*)(rd + 64))[sl];

        const __half2 z = __float2half2_rn(0.0f);
        __half2 l0 = __hmax2(__hadd2(*(const __half2*)&sa_lo.x, *(const __half2*)&da_lo.x), z);
        __half2 l1 = __hmax2(__hadd2(*(const __half2*)&sa_lo.y, *(const __half2*)&da_lo.y), z);
        __half2 h0 = __hmax2(__hadd2(*(const __half2*)&sa_hi.x, *(const __half2*)&da_hi.x), z);
        __half2 h1 = __hmax2(__hadd2(*(const __half2*)&sa_hi.y, *(const __half2*)&da_hi.y), z);

        float2 fl0 = __half22float2(l0);
        float2 fl1 = __half22float2(l1);
        float2 fh0 = __half22float2(h0);
        float2 fh1 = __half22float2(h1);

        float* ep = embs + (size_t)e * D;
        *(float4*)(ep + sl * 4)      = make_float4(fl0.x, fl0.y, fl1.x, fl1.y);
        *(float4*)(ep + 64 + sl * 4) = make_float4(fh0.x, fh0.y, fh1.x, fh1.y);

        const float4 wa_lo = ws[sl];           // row0 cols sl*4..+3
        const float4 wa_hi = ws[16 + sl];      // row0 cols 64+sl*4..+3
        const float4 wb_lo = ws[32 + sl];      // row1
        const float4 wb_hi = ws[48 + sl];

        float d0 = fl0.x*wa_lo.x + fl0.y*wa_lo.y + fl1.x*wa_lo.z + fl1.y*wa_lo.w
                 + fh0.x*wa_hi.x + fh0.y*wa_hi.y + fh1.x*wa_hi.z + fh1.y*wa_hi.w;
        float d1 = fl0.x*wb_lo.x + fl0.y*wb_lo.y + fl1.x*wb_lo.z + fl1.y*wb_lo.w
                 + fh0.x*wb_hi.x + fh0.y*wb_hi.y + fh1.x*wb_hi.z + fh1.y*wb_hi.w;

#pragma unroll
        for (int o = 8; o > 0; o >>= 1) {
            d0 += __shfl_xor_sync(0xffffffffu, d0, o);
            d1 += __shfl_xor_sync(0xffffffffu, d1, o);
        }
        if (sl == 0)
            sc[warp * 2 + sub] = make_float2(d0 + b_out[0], d1 + b_out[1]);
    }
    __syncthreads();

    const long long base = (long long)blockIdx.x * 16;
    if (tid < 16 && base + tid < E)
        ((float2*)score)[base + tid] = sc[tid];
}

extern "C" void kernel_launch(void* const* d_in, const int* in_sizes, int n_in,
                              void* d_out, int out_size)
{
    const float* x     = (const float*)d_in[0];
    const void*  src   = d_in[1];
    const void*  dst   = d_in[2];
    const float* W_src = (const float*)d_in[3];
    const float* b_src = (const float*)d_in[4];
    const float* W_dst = (const float*)d_in[5];
    const float* b_dst = (const float*)d_in[6];
    const float* W_out = (const float*)d_in[7];
    const float* b_out = (const float*)d_in[8];

    const int N = in_sizes[0] / D;
    const long long E = in_sizes[1];

    float* out   = (float*)d_out;
    float* score = out;                       // [E, 2]
    float* embs  = out + (size_t)E * 2;       // [E, 128]

    detect_idx_kernel<<<1, 1>>>((const long long*)src, N);

    const int gb = (N + 127) / 128;
    node_gemm_fused<<<gb, 512>>>(x, W_src, b_src, W_dst, b_dst, N);

    const int eb = (int)((E + 15) / 16);
    edge_kernel<<<eb, 256>>>(src, dst, W_out, b_out, score, embs, E, N);
}